// round 1
// baseline (speedup 1.0000x reference)
#include <cuda_runtime.h>
#include <cstdint>

#define NGC_MAX 100000
#define NGS_MAX 100000

// ---------------- scratch (device globals; no cudaMalloc allowed) ----------
__device__ float    g_gcx[NGC_MAX * 64];
__device__ float    g_gsx[NGS_MAX * 64];
__device__ unsigned g_aggc[NGC_MAX * 256];  // [sum f1 | max-key f2 | min-key f3 | sum f4]
__device__ unsigned g_aggs[NGS_MAX * 256];

// monotone float<->uint key for atomicMax/Min on floats
__device__ __forceinline__ unsigned fkey(float f) {
    unsigned u = __float_as_uint(f);
    return (u & 0x80000000u) ? ~u : (u | 0x80000000u);
}
__device__ __forceinline__ float fdec(unsigned k) {
    unsigned u = (k & 0x80000000u) ? (k & 0x7FFFFFFFu) : ~k;
    return __uint_as_float(u);
}

// ---------------- embedding: out[n][h] = b[h] + sum_f nf[n][f]*w[f][h] ------
__global__ void embed_kernel(const float* __restrict__ nf, const float* __restrict__ w,
                             const float* __restrict__ b, float* __restrict__ out,
                             int N, int F) {
    int idx = blockIdx.x * blockDim.x + threadIdx.x;
    if (idx >= N * 64) return;
    int n = idx >> 6, h = idx & 63;
    const float* row = nf + (size_t)n * F;
    float acc = b[h];
    for (int f = 0; f < F; f++) acc = fmaf(__ldg(row + f), __ldg(w + f * 64 + h), acc);
    out[idx] = acc;
}

// ---------------- init agg: sums=0, max-keys=0, min-keys=0xFFFFFFFF ---------
__global__ void init_agg_kernel(unsigned* __restrict__ a, int total) {
    int idx = blockIdx.x * blockDim.x + threadIdx.x;
    if (idx < total) {
        int col = idx & 255;
        a[idx] = (col >= 128 && col < 192) ? 0xFFFFFFFFu : 0u;
    }
}

// ---------------- edge kernel: gather + MLP(128->128->257) + gated atomics --
// 256 threads (8 warps), 4 edges per warp per iteration, persistent grid.
// All weights resident in SMEM.
#define EDGE_SMEM_FLOATS (16384 + 32768 + 128 + 128 + 256 + 4 + 4096 + 4096)
__global__ void __launch_bounds__(256, 1) edge_kernel(
    const float* __restrict__ srcx, const float* __restrict__ dstx,
    const int* __restrict__ src, const int* __restrict__ dst,
    const float* __restrict__ w1, const float* __restrict__ b1,
    const float* __restrict__ w2, const float* __restrict__ b2,
    unsigned* __restrict__ agg, int E) {
    extern __shared__ float sm[];
    float* s_w1  = sm;              // [128][128]
    float* s_w2f = sm + 16384;      // [128][256] (cols 1..256 of w2)
    float* s_w2g = sm + 49152;      // [128]      (col 0 of w2: gate)
    float* s_b1  = sm + 49280;      // [128]
    float* s_b2f = sm + 49408;      // [256]
    float* s_b2g = sm + 49664;      // [1] (+pad)
    float* s_xe  = sm + 49668;      // 8 warps * 4 edges * 128
    float* s_h   = sm + 53764;      // 8 warps * 4 edges * 128

    const int tid = threadIdx.x, lane = tid & 31, wid = tid >> 5;

    for (int i = tid; i < 4096; i += 256)
        ((float4*)s_w1)[i] = ((const float4*)w1)[i];
    for (int i = tid; i < 128 * 257; i += 256) {
        float v = __ldg(w2 + i);
        int r = i / 257, c = i - r * 257;
        if (c == 0) s_w2g[r] = v; else s_w2f[r * 256 + c - 1] = v;
    }
    if (tid < 128) s_b1[tid] = b1[tid];
    s_b2f[tid] = b2[tid + 1];  // 256 threads cover 256 entries... (tid<256 always)
    if (tid == 0) s_b2g[0] = b2[0];
    __syncthreads();

    float* xe = s_xe + wid * 512;
    float* hh = s_h + wid * 512;

    const int NG = (E + 3) >> 2;
    for (int g = blockIdx.x * 8 + wid; g < NG; g += gridDim.x * 8) {
        const int eb = g * 4;
        int dn[4];
        // gather: lanes 0..15 load src row (float4), 16..31 load dst row
        #pragma unroll
        for (int e = 0; e < 4; e++) {
            int eid = eb + e;
            bool valid = eid < E;
            int si = valid ? __ldg(src + eid) : 0;
            int di = valid ? __ldg(dst + eid) : 0;
            dn[e] = valid ? di : -1;
            float4 val = (lane < 16)
                ? ((const float4*)(srcx + (size_t)si * 64))[lane]
                : ((const float4*)(dstx + (size_t)di * 64))[lane - 16];
            ((float4*)(xe + e * 128))[lane] = val;
        }
        __syncwarp();

        // layer 1: h = relu(xe @ w1 + b1). lane owns cols 4*lane..+3, 4 edges.
        float4 acc[4];
        {
            float4 bv = ((float4*)s_b1)[lane];
            #pragma unroll
            for (int e = 0; e < 4; e++) acc[e] = bv;
        }
        #pragma unroll 4
        for (int i = 0; i < 128; i++) {
            float4 w = ((float4*)s_w1)[i * 32 + lane];
            #pragma unroll
            for (int e = 0; e < 4; e++) {
                float xv = xe[e * 128 + i];
                acc[e].x = fmaf(xv, w.x, acc[e].x);
                acc[e].y = fmaf(xv, w.y, acc[e].y);
                acc[e].z = fmaf(xv, w.z, acc[e].z);
                acc[e].w = fmaf(xv, w.w, acc[e].w);
            }
        }
        #pragma unroll
        for (int e = 0; e < 4; e++) {
            float4 r;
            r.x = fmaxf(acc[e].x, 0.f); r.y = fmaxf(acc[e].y, 0.f);
            r.z = fmaxf(acc[e].z, 0.f); r.w = fmaxf(acc[e].w, 0.f);
            ((float4*)(hh + e * 128))[lane] = r;
        }
        __syncwarp();

        // gate: m0 = b2[0] + h . w2[:,0], sigmoid
        float mg[4] = {0.f, 0.f, 0.f, 0.f};
        #pragma unroll
        for (int k = 0; k < 4; k++) {
            int i = lane + k * 32;
            float wg = s_w2g[i];
            #pragma unroll
            for (int e = 0; e < 4; e++) mg[e] = fmaf(hh[e * 128 + i], wg, mg[e]);
        }
        #pragma unroll
        for (int off = 16; off; off >>= 1) {
            #pragma unroll
            for (int e = 0; e < 4; e++)
                mg[e] += __shfl_xor_sync(0xffffffffu, mg[e], off);
        }
        float gt[4];
        {
            float bg = s_b2g[0];
            #pragma unroll
            for (int e = 0; e < 4; e++)
                gt[e] = 1.f / (1.f + __expf(-(mg[e] + bg)));
        }

        // layer 2 (f part): lane owns cols 8*lane..+7 of the 256 f-cols.
        float4 cA[4], cB[4];
        {
            float4 bA = ((float4*)s_b2f)[lane * 2];
            float4 bB = ((float4*)s_b2f)[lane * 2 + 1];
            #pragma unroll
            for (int e = 0; e < 4; e++) { cA[e] = bA; cB[e] = bB; }
        }
        #pragma unroll 2
        for (int i = 0; i < 128; i++) {
            float4 wA = ((float4*)s_w2f)[i * 64 + lane * 2];
            float4 wB = ((float4*)s_w2f)[i * 64 + lane * 2 + 1];
            #pragma unroll
            for (int e = 0; e < 4; e++) {
                float h = hh[e * 128 + i];
                cA[e].x = fmaf(h, wA.x, cA[e].x); cA[e].y = fmaf(h, wA.y, cA[e].y);
                cA[e].z = fmaf(h, wA.z, cA[e].z); cA[e].w = fmaf(h, wA.w, cA[e].w);
                cB[e].x = fmaf(h, wB.x, cB[e].x); cB[e].y = fmaf(h, wB.y, cB[e].y);
                cB[e].z = fmaf(h, wB.z, cB[e].z); cB[e].w = fmaf(h, wB.w, cB[e].w);
            }
        }

        // epilogue: lane/8 selects category (0:sum f1, 1:max f2, 2:min f3, 3:sum f4)
        unsigned cat = (unsigned)(lane >> 3);
        #pragma unroll
        for (int e = 0; e < 4; e++) {
            if (dn[e] < 0) continue;
            float g2 = gt[e];
            float vs[8] = {cA[e].x * g2, cA[e].y * g2, cA[e].z * g2, cA[e].w * g2,
                           cB[e].x * g2, cB[e].y * g2, cB[e].z * g2, cB[e].w * g2};
            unsigned* bp = agg + (size_t)dn[e] * 256 + lane * 8;
            if (cat == 1u) {
                #pragma unroll
                for (int t = 0; t < 8; t++) atomicMax(bp + t, fkey(vs[t]));
            } else if (cat == 2u) {
                #pragma unroll
                for (int t = 0; t < 8; t++) atomicMin(bp + t, fkey(vs[t]));
            } else {
                #pragma unroll
                for (int t = 0; t < 8; t++) atomicAdd((float*)(bp + t), vs[t]);
            }
        }
    }
}

// ---------------- node kernel: new_x = [x|agg]@rw+rb; out = mlp2([x|new_x]) -
// 256 threads: 32 nodes/tile, 8 col-groups per node. Persistent grid.
#define NODE_SMEM_FLOATS (20480 + 8192 + 4096 + 64 + 64 + 64 + 32*321 + 32*68 + 32*132)
__global__ void __launch_bounds__(256, 1) node_kernel(
    const float* __restrict__ x, const unsigned* __restrict__ agg,
    const float* __restrict__ rw, const float* __restrict__ rb,
    const float* __restrict__ w1, const float* __restrict__ b1,
    const float* __restrict__ w2, const float* __restrict__ b2,
    float* __restrict__ out, int N) {
    extern __shared__ float sm[];
    float* s_rw = sm;            // [320][64]
    float* s_w1 = sm + 20480;    // [128][64]
    float* s_w2 = sm + 28672;    // [64][64]
    float* s_rb = sm + 32768;    // [64]
    float* s_b1 = sm + 32832;    // [64]
    float* s_b2 = sm + 32896;    // [64]
    float* s_z  = sm + 32960;    // [32][321] (pad)
    float* s_nx = sm + 43232;    // [32][68]  (pad)
    float* s_h  = sm + 45408;    // [32][132] (pad)

    const int tid = threadIdx.x;
    for (int i = tid; i < 5120; i += 256) ((float4*)s_rw)[i] = ((const float4*)rw)[i];
    for (int i = tid; i < 2048; i += 256) ((float4*)s_w1)[i] = ((const float4*)w1)[i];
    for (int i = tid; i < 1024; i += 256) ((float4*)s_w2)[i] = ((const float4*)w2)[i];
    if (tid < 64) { s_rb[tid] = rb[tid]; s_b1[tid] = b1[tid]; s_b2[tid] = b2[tid]; }
    __syncthreads();

    const int n = tid >> 3, jg = tid & 7;
    const int ntiles = (N + 31) >> 5;
    for (int tile = blockIdx.x; tile < ntiles; tile += gridDim.x) {
        const int n0 = tile * 32;
        // load Z tile = [x | decoded agg] : 32 x 320
        for (int idx = tid; idx < 32 * 320; idx += 256) {
            int nn = idx / 320, i = idx - nn * 320;
            int gn = n0 + nn;
            float v = 0.f;
            if (gn < N) {
                if (i < 64) v = __ldg(x + (size_t)gn * 64 + i);
                else {
                    int col = i - 64;
                    unsigned raw = __ldg(agg + (size_t)gn * 256 + col);
                    if (col < 64 || col >= 192) v = __uint_as_float(raw);
                    else if (col < 128) v = (raw == 0u) ? 0.f : fdec(raw);          // max, untouched->0
                    else                v = (raw == 0xFFFFFFFFu) ? 0.f : fdec(raw); // min, untouched->0
                }
            }
            s_z[nn * 321 + i] = v;
        }
        __syncthreads();

        const float* zrow = s_z + n * 321;
        // stage 1: new_x[8 cols] = z(320) @ rw + rb
        float4 A = ((float4*)s_rb)[jg * 2], B = ((float4*)s_rb)[jg * 2 + 1];
        #pragma unroll 4
        for (int i = 0; i < 320; i++) {
            float zz = zrow[i];
            float4 wA = ((float4*)s_rw)[i * 16 + jg * 2];
            float4 wB = ((float4*)s_rw)[i * 16 + jg * 2 + 1];
            A.x = fmaf(zz, wA.x, A.x); A.y = fmaf(zz, wA.y, A.y);
            A.z = fmaf(zz, wA.z, A.z); A.w = fmaf(zz, wA.w, A.w);
            B.x = fmaf(zz, wB.x, B.x); B.y = fmaf(zz, wB.y, B.y);
            B.z = fmaf(zz, wB.z, B.z); B.w = fmaf(zz, wB.w, B.w);
        }
        ((float4*)(s_nx + n * 68))[jg * 2] = A;
        ((float4*)(s_nx + n * 68))[jg * 2 + 1] = B;
        __syncwarp();

        // stage 2: h[16 cols] = relu([x|new_x](128) @ w1 + b1)
        float hacc[16];
        #pragma unroll
        for (int t = 0; t < 16; t++) hacc[t] = s_b1[jg * 16 + t];
        #pragma unroll 2
        for (int i = 0; i < 64; i++) {
            float in = zrow[i];
            const float* wr = s_w1 + i * 64 + jg * 16;
            #pragma unroll
            for (int t = 0; t < 16; t++) hacc[t] = fmaf(in, wr[t], hacc[t]);
        }
        const float* nxrow = s_nx + n * 68;
        #pragma unroll 2
        for (int i = 0; i < 64; i++) {
            float in = nxrow[i];
            const float* wr = s_w1 + (64 + i) * 64 + jg * 16;
            #pragma unroll
            for (int t = 0; t < 16; t++) hacc[t] = fmaf(in, wr[t], hacc[t]);
        }
        #pragma unroll
        for (int t = 0; t < 16; t++) s_h[n * 132 + jg * 16 + t] = fmaxf(hacc[t], 0.f);
        __syncwarp();

        // stage 3: out[8 cols] = h(64) @ w2 + b2
        float4 O0 = ((float4*)s_b2)[jg * 2], O1 = ((float4*)s_b2)[jg * 2 + 1];
        const float* hrow = s_h + n * 132;
        #pragma unroll 4
        for (int i = 0; i < 64; i++) {
            float hv = hrow[i];
            float4 wA = ((float4*)s_w2)[i * 16 + jg * 2];
            float4 wB = ((float4*)s_w2)[i * 16 + jg * 2 + 1];
            O0.x = fmaf(hv, wA.x, O0.x); O0.y = fmaf(hv, wA.y, O0.y);
            O0.z = fmaf(hv, wA.z, O0.z); O0.w = fmaf(hv, wA.w, O0.w);
            O1.x = fmaf(hv, wB.x, O1.x); O1.y = fmaf(hv, wB.y, O1.y);
            O1.z = fmaf(hv, wB.z, O1.z); O1.w = fmaf(hv, wB.w, O1.w);
        }
        int gn = n0 + n;
        if (gn < N) {
            ((float4*)(out + (size_t)gn * 64 + jg * 8))[0] = O0;
            ((float4*)(out + (size_t)gn * 64 + jg * 8))[1] = O1;
        }
        __syncthreads();  // protect s_z before next tile's cooperative load
    }
}

// ---------------------------------------------------------------------------
extern "C" void kernel_launch(void* const* d_in, const int* in_sizes, int n_in,
                              void* d_out, int out_size) {
    const float* nf_gc  = (const float*)d_in[0];
    const float* nf_gs  = (const float*)d_in[1];
    const float* w_gc   = (const float*)d_in[2];
    const float* b_gc   = (const float*)d_in[3];
    const float* w_gs   = (const float*)d_in[4];
    const float* b_gs   = (const float*)d_in[5];
    const float* s2c_w1 = (const float*)d_in[6];
    const float* s2c_b1 = (const float*)d_in[7];
    const float* s2c_w2 = (const float*)d_in[8];
    const float* s2c_b2 = (const float*)d_in[9];
    const float* s2c_rw = (const float*)d_in[10];
    const float* s2c_rb = (const float*)d_in[11];
    const float* c2s_w1 = (const float*)d_in[12];
    const float* c2s_b1 = (const float*)d_in[13];
    const float* c2s_w2 = (const float*)d_in[14];
    const float* c2s_b2 = (const float*)d_in[15];
    const float* c2s_rw = (const float*)d_in[16];
    const float* c2s_rb = (const float*)d_in[17];
    const float* gc_w1  = (const float*)d_in[18];
    const float* gc_b1  = (const float*)d_in[19];
    const float* gc_w2  = (const float*)d_in[20];
    const float* gc_b2  = (const float*)d_in[21];
    const float* gs_w1  = (const float*)d_in[22];
    const float* gs_b1  = (const float*)d_in[23];
    const float* gs_w2  = (const float*)d_in[24];
    const float* gs_b2  = (const float*)d_in[25];
    const int* s2c_src  = (const int*)d_in[26];
    const int* s2c_dst  = (const int*)d_in[27];
    const int* c2s_src  = (const int*)d_in[28];
    const int* c2s_dst  = (const int*)d_in[29];

    const int FGC = in_sizes[2] / 64;
    const int FGS = in_sizes[4] / 64;
    const int NGC = in_sizes[0] / FGC;
    const int NGS = in_sizes[1] / FGS;
    const int E1 = in_sizes[26];
    const int E2 = in_sizes[28];

    float *gcx, *gsx;
    unsigned *aggc, *aggs;
    cudaGetSymbolAddress((void**)&gcx, g_gcx);
    cudaGetSymbolAddress((void**)&gsx, g_gsx);
    cudaGetSymbolAddress((void**)&aggc, g_aggc);
    cudaGetSymbolAddress((void**)&aggs, g_aggs);

    const int EDGE_SMEM = EDGE_SMEM_FLOATS * 4;  // 223248 B
    const int NODE_SMEM = NODE_SMEM_FLOATS * 4;  // 198528 B
    cudaFuncSetAttribute(edge_kernel, cudaFuncAttributeMaxDynamicSharedMemorySize, EDGE_SMEM);
    cudaFuncSetAttribute(node_kernel, cudaFuncAttributeMaxDynamicSharedMemorySize, NODE_SMEM);

    embed_kernel<<<(NGC * 64 + 255) / 256, 256>>>(nf_gc, w_gc, b_gc, gcx, NGC, FGC);
    embed_kernel<<<(NGS * 64 + 255) / 256, 256>>>(nf_gs, w_gs, b_gs, gsx, NGS, FGS);
    init_agg_kernel<<<(NGC * 256 + 255) / 256, 256>>>(aggc, NGC * 256);
    init_agg_kernel<<<(NGS * 256 + 255) / 256, 256>>>(aggs, NGS * 256);

    // gs -> gc
    edge_kernel<<<152, 256, EDGE_SMEM>>>(gsx, gcx, s2c_src, s2c_dst,
                                         s2c_w1, s2c_b1, s2c_w2, s2c_b2, aggc, E1);
    // gc -> gs
    edge_kernel<<<152, 256, EDGE_SMEM>>>(gcx, gsx, c2s_src, c2s_dst,
                                         c2s_w1, c2s_b1, c2s_w2, c2s_b2, aggs, E2);

    float* out = (float*)d_out;
    node_kernel<<<152, 256, NODE_SMEM>>>(gcx, aggc, s2c_rw, s2c_rb,
                                         gc_w1, gc_b1, gc_w2, gc_b2, out, NGC);
    node_kernel<<<152, 256, NODE_SMEM>>>(gsx, aggs, c2s_rw, c2s_rb,
                                         gs_w1, gs_b1, gs_w2, gs_b2, out + (size_t)NGC * 64, NGS);
}

// round 2
// speedup vs baseline: 1.0004x; 1.0004x over previous
#include <cuda_runtime.h>
#include <cstdint>

#define NGC_MAX 100000
#define NGS_MAX 100000

// ---------------- scratch (device globals; no cudaMalloc allowed) ----------
__device__ float    g_gcx[NGC_MAX * 64];
__device__ float    g_gsx[NGS_MAX * 64];
__device__ unsigned g_aggc[NGC_MAX * 256];  // [sum f1 | max-key f2 | min-key f3 | sum f4]
__device__ unsigned g_aggs[NGS_MAX * 256];

// monotone float<->uint key for atomicMax/Min on floats
__device__ __forceinline__ unsigned fkey(float f) {
    unsigned u = __float_as_uint(f);
    return (u & 0x80000000u) ? ~u : (u | 0x80000000u);
}
__device__ __forceinline__ float fdec(unsigned k) {
    unsigned u = (k & 0x80000000u) ? (k & 0x7FFFFFFFu) : ~k;
    return __uint_as_float(u);
}

// ---------------- embedding: out[n][h] = b[h] + sum_f nf[n][f]*w[f][h] ------
__global__ void embed_kernel(const float* __restrict__ nf, const float* __restrict__ w,
                             const float* __restrict__ b, float* __restrict__ out,
                             int N, int F) {
    int idx = blockIdx.x * blockDim.x + threadIdx.x;
    if (idx >= N * 64) return;
    int n = idx >> 6, h = idx & 63;
    const float* row = nf + (size_t)n * F;
    float acc = b[h];
    for (int f = 0; f < F; f++) acc = fmaf(__ldg(row + f), __ldg(w + f * 64 + h), acc);
    out[idx] = acc;
}

// ---------------- init agg: sums=0, max-keys=0, min-keys=0xFFFFFFFF ---------
__global__ void init_agg_kernel(unsigned* __restrict__ a, int total) {
    int idx = blockIdx.x * blockDim.x + threadIdx.x;
    if (idx < total) {
        int col = idx & 255;
        a[idx] = (col >= 128 && col < 192) ? 0xFFFFFFFFu : 0u;
    }
}

// ---------------- edge kernel: gather + MLP(128->128->257) + gated atomics --
// 256 threads (8 warps), 4 edges per warp per iteration, persistent grid.
// All weights resident in SMEM.
#define EDGE_SMEM_FLOATS (16384 + 32768 + 128 + 128 + 256 + 4 + 4096 + 4096)
__global__ void __launch_bounds__(256, 1) edge_kernel(
    const float* __restrict__ srcx, const float* __restrict__ dstx,
    const int* __restrict__ src, const int* __restrict__ dst,
    const float* __restrict__ w1, const float* __restrict__ b1,
    const float* __restrict__ w2, const float* __restrict__ b2,
    unsigned* __restrict__ agg, int E) {
    extern __shared__ float sm[];
    float* s_w1  = sm;              // [128][128]
    float* s_w2f = sm + 16384;      // [128][256] (cols 1..256 of w2)
    float* s_w2g = sm + 49152;      // [128]      (col 0 of w2: gate)
    float* s_b1  = sm + 49280;      // [128]
    float* s_b2f = sm + 49408;      // [256]
    float* s_b2g = sm + 49664;      // [1] (+pad)
    float* s_xe  = sm + 49668;      // 8 warps * 4 edges * 128
    float* s_h   = sm + 53764;      // 8 warps * 4 edges * 128

    const int tid = threadIdx.x, lane = tid & 31, wid = tid >> 5;

    for (int i = tid; i < 4096; i += 256)
        ((float4*)s_w1)[i] = ((const float4*)w1)[i];
    for (int i = tid; i < 128 * 257; i += 256) {
        float v = __ldg(w2 + i);
        int r = i / 257, c = i - r * 257;
        if (c == 0) s_w2g[r] = v; else s_w2f[r * 256 + c - 1] = v;
    }
    if (tid < 128) s_b1[tid] = b1[tid];
    s_b2f[tid] = b2[tid + 1];  // 256 threads cover 256 entries... (tid<256 always)
    if (tid == 0) s_b2g[0] = b2[0];
    __syncthreads();

    float* xe = s_xe + wid * 512;
    float* hh = s_h + wid * 512;

    const int NG = (E + 3) >> 2;
    for (int g = blockIdx.x * 8 + wid; g < NG; g += gridDim.x * 8) {
        const int eb = g * 4;
        int dn[4];
        // gather: lanes 0..15 load src row (float4), 16..31 load dst row
        #pragma unroll
        for (int e = 0; e < 4; e++) {
            int eid = eb + e;
            bool valid = eid < E;
            int si = valid ? __ldg(src + eid) : 0;
            int di = valid ? __ldg(dst + eid) : 0;
            dn[e] = valid ? di : -1;
            float4 val = (lane < 16)
                ? ((const float4*)(srcx + (size_t)si * 64))[lane]
                : ((const float4*)(dstx + (size_t)di * 64))[lane - 16];
            ((float4*)(xe + e * 128))[lane] = val;
        }
        __syncwarp();

        // layer 1: h = relu(xe @ w1 + b1). lane owns cols 4*lane..+3, 4 edges.
        float4 acc[4];
        {
            float4 bv = ((float4*)s_b1)[lane];
            #pragma unroll
            for (int e = 0; e < 4; e++) acc[e] = bv;
        }
        #pragma unroll 4
        for (int i = 0; i < 128; i++) {
            float4 w = ((float4*)s_w1)[i * 32 + lane];
            #pragma unroll
            for (int e = 0; e < 4; e++) {
                float xv = xe[e * 128 + i];
                acc[e].x = fmaf(xv, w.x, acc[e].x);
                acc[e].y = fmaf(xv, w.y, acc[e].y);
                acc[e].z = fmaf(xv, w.z, acc[e].z);
                acc[e].w = fmaf(xv, w.w, acc[e].w);
            }
        }
        #pragma unroll
        for (int e = 0; e < 4; e++) {
            float4 r;
            r.x = fmaxf(acc[e].x, 0.f); r.y = fmaxf(acc[e].y, 0.f);
            r.z = fmaxf(acc[e].z, 0.f); r.w = fmaxf(acc[e].w, 0.f);
            ((float4*)(hh + e * 128))[lane] = r;
        }
        __syncwarp();

        // gate: m0 = b2[0] + h . w2[:,0], sigmoid
        float mg[4] = {0.f, 0.f, 0.f, 0.f};
        #pragma unroll
        for (int k = 0; k < 4; k++) {
            int i = lane + k * 32;
            float wg = s_w2g[i];
            #pragma unroll
            for (int e = 0; e < 4; e++) mg[e] = fmaf(hh[e * 128 + i], wg, mg[e]);
        }
        #pragma unroll
        for (int off = 16; off; off >>= 1) {
            #pragma unroll
            for (int e = 0; e < 4; e++)
                mg[e] += __shfl_xor_sync(0xffffffffu, mg[e], off);
        }
        float gt[4];
        {
            float bg = s_b2g[0];
            #pragma unroll
            for (int e = 0; e < 4; e++)
                gt[e] = 1.f / (1.f + __expf(-(mg[e] + bg)));
        }

        // layer 2 (f part): lane owns cols 8*lane..+7 of the 256 f-cols.
        float4 cA[4], cB[4];
        {
            float4 bA = ((float4*)s_b2f)[lane * 2];
            float4 bB = ((float4*)s_b2f)[lane * 2 + 1];
            #pragma unroll
            for (int e = 0; e < 4; e++) { cA[e] = bA; cB[e] = bB; }
        }
        #pragma unroll 2
        for (int i = 0; i < 128; i++) {
            float4 wA = ((float4*)s_w2f)[i * 64 + lane * 2];
            float4 wB = ((float4*)s_w2f)[i * 64 + lane * 2 + 1];
            #pragma unroll
            for (int e = 0; e < 4; e++) {
                float h = hh[e * 128 + i];
                cA[e].x = fmaf(h, wA.x, cA[e].x); cA[e].y = fmaf(h, wA.y, cA[e].y);
                cA[e].z = fmaf(h, wA.z, cA[e].z); cA[e].w = fmaf(h, wA.w, cA[e].w);
                cB[e].x = fmaf(h, wB.x, cB[e].x); cB[e].y = fmaf(h, wB.y, cB[e].y);
                cB[e].z = fmaf(h, wB.z, cB[e].z); cB[e].w = fmaf(h, wB.w, cB[e].w);
            }
        }

        // epilogue: lane/8 selects category (0:sum f1, 1:max f2, 2:min f3, 3:sum f4)
        unsigned cat = (unsigned)(lane >> 3);
        #pragma unroll
        for (int e = 0; e < 4; e++) {
            if (dn[e] < 0) continue;
            float g2 = gt[e];
            float vs[8] = {cA[e].x * g2, cA[e].y * g2, cA[e].z * g2, cA[e].w * g2,
                           cB[e].x * g2, cB[e].y * g2, cB[e].z * g2, cB[e].w * g2};
            unsigned* bp = agg + (size_t)dn[e] * 256 + lane * 8;
            if (cat == 1u) {
                #pragma unroll
                for (int t = 0; t < 8; t++) atomicMax(bp + t, fkey(vs[t]));
            } else if (cat == 2u) {
                #pragma unroll
                for (int t = 0; t < 8; t++) atomicMin(bp + t, fkey(vs[t]));
            } else {
                #pragma unroll
                for (int t = 0; t < 8; t++) atomicAdd((float*)(bp + t), vs[t]);
            }
        }
    }
}

// ---------------- node kernel: new_x = [x|agg]@rw+rb; out = mlp2([x|new_x]) -
// 256 threads: 32 nodes/tile, 8 col-groups per node. Persistent grid.
#define NODE_SMEM_FLOATS (20480 + 8192 + 4096 + 64 + 64 + 64 + 32*321 + 32*68 + 32*132)
__global__ void __launch_bounds__(256, 1) node_kernel(
    const float* __restrict__ x, const unsigned* __restrict__ agg,
    const float* __restrict__ rw, const float* __restrict__ rb,
    const float* __restrict__ w1, const float* __restrict__ b1,
    const float* __restrict__ w2, const float* __restrict__ b2,
    float* __restrict__ out, int N) {
    extern __shared__ float sm[];
    float* s_rw = sm;            // [320][64]
    float* s_w1 = sm + 20480;    // [128][64]
    float* s_w2 = sm + 28672;    // [64][64]
    float* s_rb = sm + 32768;    // [64]
    float* s_b1 = sm + 32832;    // [64]
    float* s_b2 = sm + 32896;    // [64]
    float* s_z  = sm + 32960;    // [32][321] (pad)
    float* s_nx = sm + 43232;    // [32][68]  (pad)
    float* s_h  = sm + 45408;    // [32][132] (pad)

    const int tid = threadIdx.x;
    for (int i = tid; i < 5120; i += 256) ((float4*)s_rw)[i] = ((const float4*)rw)[i];
    for (int i = tid; i < 2048; i += 256) ((float4*)s_w1)[i] = ((const float4*)w1)[i];
    for (int i = tid; i < 1024; i += 256) ((float4*)s_w2)[i] = ((const float4*)w2)[i];
    if (tid < 64) { s_rb[tid] = rb[tid]; s_b1[tid] = b1[tid]; s_b2[tid] = b2[tid]; }
    __syncthreads();

    const int n = tid >> 3, jg = tid & 7;
    const int ntiles = (N + 31) >> 5;
    for (int tile = blockIdx.x; tile < ntiles; tile += gridDim.x) {
        const int n0 = tile * 32;
        // load Z tile = [x | decoded agg] : 32 x 320
        for (int idx = tid; idx < 32 * 320; idx += 256) {
            int nn = idx / 320, i = idx - nn * 320;
            int gn = n0 + nn;
            float v = 0.f;
            if (gn < N) {
                if (i < 64) v = __ldg(x + (size_t)gn * 64 + i);
                else {
                    int col = i - 64;
                    unsigned raw = __ldg(agg + (size_t)gn * 256 + col);
                    if (col < 64 || col >= 192) v = __uint_as_float(raw);
                    else if (col < 128) v = (raw == 0u) ? 0.f : fdec(raw);          // max, untouched->0
                    else                v = (raw == 0xFFFFFFFFu) ? 0.f : fdec(raw); // min, untouched->0
                }
            }
            s_z[nn * 321 + i] = v;
        }
        __syncthreads();

        const float* zrow = s_z + n * 321;
        // stage 1: new_x[8 cols] = z(320) @ rw + rb
        float4 A = ((float4*)s_rb)[jg * 2], B = ((float4*)s_rb)[jg * 2 + 1];
        #pragma unroll 4
        for (int i = 0; i < 320; i++) {
            float zz = zrow[i];
            float4 wA = ((float4*)s_rw)[i * 16 + jg * 2];
            float4 wB = ((float4*)s_rw)[i * 16 + jg * 2 + 1];
            A.x = fmaf(zz, wA.x, A.x); A.y = fmaf(zz, wA.y, A.y);
            A.z = fmaf(zz, wA.z, A.z); A.w = fmaf(zz, wA.w, A.w);
            B.x = fmaf(zz, wB.x, B.x); B.y = fmaf(zz, wB.y, B.y);
            B.z = fmaf(zz, wB.z, B.z); B.w = fmaf(zz, wB.w, B.w);
        }
        ((float4*)(s_nx + n * 68))[jg * 2] = A;
        ((float4*)(s_nx + n * 68))[jg * 2 + 1] = B;
        __syncwarp();

        // stage 2: h[16 cols] = relu([x|new_x](128) @ w1 + b1)
        float hacc[16];
        #pragma unroll
        for (int t = 0; t < 16; t++) hacc[t] = s_b1[jg * 16 + t];
        #pragma unroll 2
        for (int i = 0; i < 64; i++) {
            float in = zrow[i];
            const float* wr = s_w1 + i * 64 + jg * 16;
            #pragma unroll
            for (int t = 0; t < 16; t++) hacc[t] = fmaf(in, wr[t], hacc[t]);
        }
        const float* nxrow = s_nx + n * 68;
        #pragma unroll 2
        for (int i = 0; i < 64; i++) {
            float in = nxrow[i];
            const float* wr = s_w1 + (64 + i) * 64 + jg * 16;
            #pragma unroll
            for (int t = 0; t < 16; t++) hacc[t] = fmaf(in, wr[t], hacc[t]);
        }
        #pragma unroll
        for (int t = 0; t < 16; t++) s_h[n * 132 + jg * 16 + t] = fmaxf(hacc[t], 0.f);
        __syncwarp();

        // stage 3: out[8 cols] = h(64) @ w2 + b2
        float4 O0 = ((float4*)s_b2)[jg * 2], O1 = ((float4*)s_b2)[jg * 2 + 1];
        const float* hrow = s_h + n * 132;
        #pragma unroll 4
        for (int i = 0; i < 64; i++) {
            float hv = hrow[i];
            float4 wA = ((float4*)s_w2)[i * 16 + jg * 2];
            float4 wB = ((float4*)s_w2)[i * 16 + jg * 2 + 1];
            O0.x = fmaf(hv, wA.x, O0.x); O0.y = fmaf(hv, wA.y, O0.y);
            O0.z = fmaf(hv, wA.z, O0.z); O0.w = fmaf(hv, wA.w, O0.w);
            O1.x = fmaf(hv, wB.x, O1.x); O1.y = fmaf(hv, wB.y, O1.y);
            O1.z = fmaf(hv, wB.z, O1.z); O1.w = fmaf(hv, wB.w, O1.w);
        }
        int gn = n0 + n;
        if (gn < N) {
            ((float4*)(out + (size_t)gn * 64 + jg * 8))[0] = O0;
            ((float4*)(out + (size_t)gn * 64 + jg * 8))[1] = O1;
        }
        __syncthreads();  // protect s_z before next tile's cooperative load
    }
}

// ---------------------------------------------------------------------------
extern "C" void kernel_launch(void* const* d_in, const int* in_sizes, int n_in,
                              void* d_out, int out_size) {
    const float* nf_gc  = (const float*)d_in[0];
    const float* nf_gs  = (const float*)d_in[1];
    const float* w_gc   = (const float*)d_in[2];
    const float* b_gc   = (const float*)d_in[3];
    const float* w_gs   = (const float*)d_in[4];
    const float* b_gs   = (const float*)d_in[5];
    const float* s2c_w1 = (const float*)d_in[6];
    const float* s2c_b1 = (const float*)d_in[7];
    const float* s2c_w2 = (const float*)d_in[8];
    const float* s2c_b2 = (const float*)d_in[9];
    const float* s2c_rw = (const float*)d_in[10];
    const float* s2c_rb = (const float*)d_in[11];
    const float* c2s_w1 = (const float*)d_in[12];
    const float* c2s_b1 = (const float*)d_in[13];
    const float* c2s_w2 = (const float*)d_in[14];
    const float* c2s_b2 = (const float*)d_in[15];
    const float* c2s_rw = (const float*)d_in[16];
    const float* c2s_rb = (const float*)d_in[17];
    const float* gc_w1  = (const float*)d_in[18];
    const float* gc_b1  = (const float*)d_in[19];
    const float* gc_w2  = (const float*)d_in[20];
    const float* gc_b2  = (const float*)d_in[21];
    const float* gs_w1  = (const float*)d_in[22];
    const float* gs_b1  = (const float*)d_in[23];
    const float* gs_w2  = (const float*)d_in[24];
    const float* gs_b2  = (const float*)d_in[25];
    const int* s2c_src  = (const int*)d_in[26];
    const int* s2c_dst  = (const int*)d_in[27];
    const int* c2s_src  = (const int*)d_in[28];
    const int* c2s_dst  = (const int*)d_in[29];

    const int FGC = in_sizes[2] / 64;
    const int FGS = in_sizes[4] / 64;
    const int NGC = in_sizes[0] / FGC;
    const int NGS = in_sizes[1] / FGS;
    const int E1 = in_sizes[26];
    const int E2 = in_sizes[28];

    float *gcx, *gsx;
    unsigned *aggc, *aggs;
    cudaGetSymbolAddress((void**)&gcx, g_gcx);
    cudaGetSymbolAddress((void**)&gsx, g_gsx);
    cudaGetSymbolAddress((void**)&aggc, g_aggc);
    cudaGetSymbolAddress((void**)&aggs, g_aggs);

    const int EDGE_SMEM = EDGE_SMEM_FLOATS * 4;  // 223248 B
    const int NODE_SMEM = NODE_SMEM_FLOATS * 4;  // 198528 B
    cudaFuncSetAttribute(edge_kernel, cudaFuncAttributeMaxDynamicSharedMemorySize, EDGE_SMEM);
    cudaFuncSetAttribute(node_kernel, cudaFuncAttributeMaxDynamicSharedMemorySize, NODE_SMEM);

    embed_kernel<<<(NGC * 64 + 255) / 256, 256>>>(nf_gc, w_gc, b_gc, gcx, NGC, FGC);
    embed_kernel<<<(NGS * 64 + 255) / 256, 256>>>(nf_gs, w_gs, b_gs, gsx, NGS, FGS);
    init_agg_kernel<<<(NGC * 256 + 255) / 256, 256>>>(aggc, NGC * 256);
    init_agg_kernel<<<(NGS * 256 + 255) / 256, 256>>>(aggs, NGS * 256);

    // gs -> gc
    edge_kernel<<<152, 256, EDGE_SMEM>>>(gsx, gcx, s2c_src, s2c_dst,
                                         s2c_w1, s2c_b1, s2c_w2, s2c_b2, aggc, E1);
    // gc -> gs
    edge_kernel<<<152, 256, EDGE_SMEM>>>(gcx, gsx, c2s_src, c2s_dst,
                                         c2s_w1, c2s_b1, c2s_w2, c2s_b2, aggs, E2);

    float* out = (float*)d_out;
    node_kernel<<<152, 256, NODE_SMEM>>>(gcx, aggc, s2c_rw, s2c_rb,
                                         gc_w1, gc_b1, gc_w2, gc_b2, out, NGC);
    node_kernel<<<152, 256, NODE_SMEM>>>(gsx, aggs, c2s_rw, c2s_rb,
                                         gs_w1, gs_b1, gs_w2, gs_b2, out + (size_t)NGC * 64, NGS);
}

// round 5
// speedup vs baseline: 1.1636x; 1.1631x over previous
#include <cuda_runtime.h>
#include <cuda_bf16.h>
#include <cstdint>

#define NGC_MAX 100000
#define NGS_MAX 100000
#define EPAD 300032

__device__ float    g_gcx[NGC_MAX * 64];
__device__ float    g_gsx[NGS_MAX * 64];
__device__ unsigned g_aggc[NGC_MAX * 256];
__device__ unsigned g_aggs[NGS_MAX * 256];
__device__ unsigned g_hbuf[(size_t)EPAD * 128];   // packed (bf16 hi | bf16 lo)

__device__ __forceinline__ unsigned fkey(float f) {
    unsigned u = __float_as_uint(f);
    return (u & 0x80000000u) ? ~u : (u | 0x80000000u);
}
__device__ __forceinline__ float fdec(unsigned k) {
    unsigned u = (k & 0x80000000u) ? (k & 0x7FFFFFFFu) : ~k;
    return __uint_as_float(u);
}
__device__ __forceinline__ uint32_t smem_to_u32(const void* p) {
    uint32_t a;
    asm("{ .reg .u64 t; cvta.to.shared.u64 t, %1; cvt.u32.u64 %0, t; }" : "=r"(a) : "l"(p));
    return a;
}
__device__ __forceinline__ void ldsm_x4(uint32_t a[4], uint32_t addr) {
    asm volatile("ldmatrix.sync.aligned.m8n8.x4.shared.b16 {%0,%1,%2,%3}, [%4];"
        : "=r"(a[0]), "=r"(a[1]), "=r"(a[2]), "=r"(a[3]) : "r"(addr));
}
// NON-trans: B stored [n][k]; fragment = B[k][n] col layout for mma.row.col
__device__ __forceinline__ void ldsm_x2(uint32_t b[2], uint32_t addr) {
    asm volatile("ldmatrix.sync.aligned.m8n8.x2.shared.b16 {%0,%1}, [%2];"
        : "=r"(b[0]), "=r"(b[1]) : "r"(addr));
}
__device__ __forceinline__ void mma_bf16(float c[4], const uint32_t a[4], const uint32_t b[2]) {
    asm volatile("mma.sync.aligned.m16n8k16.row.col.f32.bf16.bf16.f32 "
        "{%0,%1,%2,%3}, {%4,%5,%6,%7}, {%8,%9}, {%0,%1,%2,%3};"
        : "+f"(c[0]), "+f"(c[1]), "+f"(c[2]), "+f"(c[3])
        : "r"(a[0]), "r"(a[1]), "r"(a[2]), "r"(a[3]), "r"(b[0]), "r"(b[1]));
}
__device__ __forceinline__ void split2(float a, float b, uint32_t& hi, uint32_t& lo) {
    __nv_bfloat16 ah = __float2bfloat16_rn(a), bh = __float2bfloat16_rn(b);
    __nv_bfloat16 al = __float2bfloat16_rn(a - __bfloat162float(ah));
    __nv_bfloat16 bl = __float2bfloat16_rn(b - __bfloat162float(bh));
    hi = (uint32_t)__bfloat16_as_ushort(ah) | ((uint32_t)__bfloat16_as_ushort(bh) << 16);
    lo = (uint32_t)__bfloat16_as_ushort(al) | ((uint32_t)__bfloat16_as_ushort(bl) << 16);
}
__device__ __forceinline__ uint32_t packhl(float v) {
    __nv_bfloat16 h = __float2bfloat16_rn(v);
    __nv_bfloat16 l = __float2bfloat16_rn(v - __bfloat162float(h));
    return (uint32_t)__bfloat16_as_ushort(h) | ((uint32_t)__bfloat16_as_ushort(l) << 16);
}
__device__ __forceinline__ float bfu(unsigned short s) {
    return __bfloat162float(__ushort_as_bfloat16(s));
}

// ---------------- embed + init ----------------
__global__ void embed_kernel(const float* __restrict__ nf, const float* __restrict__ w,
                             const float* __restrict__ b, float* __restrict__ out, int N, int F) {
    int idx = blockIdx.x * blockDim.x + threadIdx.x;
    if (idx >= N * 64) return;
    int n = idx >> 6, h = idx & 63;
    const float* row = nf + (size_t)n * F;
    float acc = b[h];
    for (int f = 0; f < F; f++) acc = fmaf(__ldg(row + f), __ldg(w + f * 64 + h), acc);
    out[idx] = acc;
}
__global__ void init_agg_kernel(unsigned* __restrict__ a, int total) {
    int idx = blockIdx.x * blockDim.x + threadIdx.x;
    if (idx < total) {
        int col = idx & 255;
        a[idx] = (col >= 128 && col < 192) ? 0xFFFFFFFFu : 0u;
    }
}

// ================= E1: layer1 via mma (h = relu(xe@w1+b1) -> hbuf) =========
#define PAD 136
#define E1_XH 0
#define E1_XL 34816
#define E1_WH 69632
#define E1_WL 104448
#define E1_B1 139264
#define E1_SMEM 139776

__global__ void __launch_bounds__(256, 1) edge_l1_kernel(
    const float* __restrict__ srcx, const float* __restrict__ dstx,
    const int* __restrict__ src, const int* __restrict__ dst,
    const float* __restrict__ w1, const float* __restrict__ b1,
    unsigned* __restrict__ hbuf, int E) {
    extern __shared__ char sm[];
    const uint32_t smb = smem_to_u32(sm);
    const int tid = threadIdx.x, lane = tid & 31, wid = tid >> 5;
    __nv_bfloat16* s_wh = (__nv_bfloat16*)(sm + E1_WH);
    __nv_bfloat16* s_wl = (__nv_bfloat16*)(sm + E1_WL);
    float* s_b1 = (float*)(sm + E1_B1);

    // stage w1: global [k=128][n=128] -> smem [n][k] hi/lo
    for (int idx = tid; idx < 128 * 128; idx += 256) {
        int k = idx >> 7, n = idx & 127;
        float w = __ldg(w1 + idx);
        __nv_bfloat16 h = __float2bfloat16_rn(w);
        __nv_bfloat16 l = __float2bfloat16_rn(w - __bfloat162float(h));
        s_wh[n * PAD + k] = h;
        s_wl[n * PAD + k] = l;
    }
    if (tid < 128) s_b1[tid] = __ldg(b1 + tid);
    __syncthreads();

    // hoist B fragments: warp owns cols n0=wid*16
    uint32_t Bh[2][8][2], Bl[2][8][2];
    #pragma unroll
    for (int nf = 0; nf < 2; nf++)
        #pragma unroll
        for (int kf = 0; kf < 8; kf++) {
            uint32_t off = (uint32_t)((wid * 16 + nf * 8 + (lane & 7)) * PAD
                            + kf * 16 + (((lane >> 3) & 1) << 3)) * 2;
            ldsm_x2(Bh[nf][kf], smb + E1_WH + off);
            ldsm_x2(Bl[nf][kf], smb + E1_WL + off);
        }

    const int ntiles = (E + 127) >> 7;
    for (int t = blockIdx.x; t < ntiles; t += gridDim.x) {
        const int tb = t * 128;
        __syncthreads();
        // gather xe=[src|dst] split bf16 hi/lo
        for (int idx = tid; idx < 4096; idx += 256) {
            int row = idx >> 5, q = idx & 31;
            int e = tb + row;
            int half = q >> 4, qq = q & 15;
            const float4* rp;
            if (half == 0) {
                int si = (e < E) ? __ldg(src + e) : 0;
                rp = (const float4*)(srcx + (size_t)si * 64);
            } else {
                int di = (e < E) ? __ldg(dst + e) : 0;
                rp = (const float4*)(dstx + (size_t)di * 64);
            }
            float4 v = __ldg(rp + qq);
            int col = half * 64 + qq * 4;
            uint32_t h01, l01, h23, l23;
            split2(v.x, v.y, h01, l01);
            split2(v.z, v.w, h23, l23);
            *(uint32_t*)(sm + E1_XH + (row * PAD + col) * 2) = h01;
            *(uint32_t*)(sm + E1_XH + (row * PAD + col) * 2 + 4) = h23;
            *(uint32_t*)(sm + E1_XL + (row * PAD + col) * 2) = l01;
            *(uint32_t*)(sm + E1_XL + (row * PAD + col) * 2 + 4) = l23;
        }
        __syncthreads();

        #pragma unroll 1
        for (int mt = 0; mt < 8; mt++) {
            float c[2][4] = {};
            #pragma unroll
            for (int kf = 0; kf < 8; kf++) {
                uint32_t Ah[4], Al[4];
                uint32_t aoff = (uint32_t)((mt * 16 + (lane & 15)) * PAD
                                 + kf * 16 + ((lane >> 4) << 3)) * 2;
                ldsm_x4(Ah, smb + E1_XH + aoff);
                ldsm_x4(Al, smb + E1_XL + aoff);
                #pragma unroll
                for (int nf = 0; nf < 2; nf++) {
                    mma_bf16(c[nf], Ah, Bh[nf][kf]);
                    mma_bf16(c[nf], Ah, Bl[nf][kf]);
                    mma_bf16(c[nf], Al, Bh[nf][kf]);
                }
            }
            int r0 = mt * 16 + (lane >> 2), r1 = r0 + 8;
            bool k0 = tb + r0 < E, k1 = tb + r1 < E;
            #pragma unroll
            for (int nf = 0; nf < 2; nf++) {
                int col0 = wid * 16 + nf * 8 + (lane & 3) * 2;
                float b0v = s_b1[col0], b1v = s_b1[col0 + 1];
                uint32_t p0 = packhl(fmaxf(c[nf][0] + b0v, 0.f));
                uint32_t p1 = packhl(fmaxf(c[nf][1] + b1v, 0.f));
                uint32_t q0 = packhl(fmaxf(c[nf][2] + b0v, 0.f));
                uint32_t q1 = packhl(fmaxf(c[nf][3] + b1v, 0.f));
                if (k0) *(uint2*)(hbuf + (size_t)(tb + r0) * 128 + col0) = make_uint2(p0, p1);
                if (k1) *(uint2*)(hbuf + (size_t)(tb + r1) * 128 + col0) = make_uint2(q0, q1);
            }
        }
    }
}

// ================= E2: layer2 + gate + segment atomics ======================
#define E2_HH 0
#define E2_HL 34816
#define E2_WH 69632
#define E2_WL 139264
#define E2_WG 208896
#define E2_B2F 209408
#define E2_GATE 210432
#define E2_DST 210944
#define E2_BG 211456
#define E2_SMEM 211472

__global__ void __launch_bounds__(256, 1) edge_l2_kernel(
    const int* __restrict__ dst,
    const float* __restrict__ w2, const float* __restrict__ b2,
    const unsigned* __restrict__ hbuf,
    unsigned* __restrict__ agg, int E) {
    extern __shared__ char sm[];
    const uint32_t smb = smem_to_u32(sm);
    const int tid = threadIdx.x, lane = tid & 31, wid = tid >> 5;
    __nv_bfloat16* s_wh = (__nv_bfloat16*)(sm + E2_WH);
    __nv_bfloat16* s_wl = (__nv_bfloat16*)(sm + E2_WL);
    unsigned short* s_hh = (unsigned short*)(sm + E2_HH);
    unsigned short* s_hl = (unsigned short*)(sm + E2_HL);
    float* s_wg = (float*)(sm + E2_WG);
    float* s_b2f = (float*)(sm + E2_B2F);
    float* s_gate = (float*)(sm + E2_GATE);
    int* s_dst = (int*)(sm + E2_DST);
    float* s_bg = (float*)(sm + E2_BG);

    // stage w2: global [k=128][257] (col0 = gate) -> smem [n=256][k] hi/lo
    for (int idx = tid; idx < 128 * 256; idx += 256) {
        int k = idx >> 8, n = idx & 255;
        float w = __ldg(w2 + k * 257 + 1 + n);
        __nv_bfloat16 h = __float2bfloat16_rn(w);
        __nv_bfloat16 l = __float2bfloat16_rn(w - __bfloat162float(h));
        s_wh[n * PAD + k] = h;
        s_wl[n * PAD + k] = l;
    }
    if (tid < 128) s_wg[tid] = __ldg(w2 + tid * 257);
    s_b2f[tid] = __ldg(b2 + 1 + tid);
    if (tid == 0) s_bg[0] = __ldg(b2);
    __syncthreads();

    // hoist B-hi fragments: warp owns cols n0w=wid*32 (one category per warp)
    uint32_t Bh[4][8][2];
    #pragma unroll
    for (int nf = 0; nf < 4; nf++)
        #pragma unroll
        for (int kf = 0; kf < 8; kf++) {
            uint32_t off = (uint32_t)((wid * 32 + nf * 8 + (lane & 7)) * PAD
                            + kf * 16 + (((lane >> 3) & 1) << 3)) * 2;
            ldsm_x2(Bh[nf][kf], smb + E2_WH + off);
        }
    const int cat = wid >> 1;

    const int ntiles = (E + 127) >> 7;
    for (int t = blockIdx.x; t < ntiles; t += gridDim.x) {
        const int tb = t * 128;
        __syncthreads();
        // stage h tile (unpack hi/lo) + dst idx
        for (int idx = tid; idx < 16384; idx += 256) {
            int row = idx >> 7, col = idx & 127;
            unsigned u = __ldg(hbuf + (size_t)(tb + row) * 128 + col);
            s_hh[row * PAD + col] = (unsigned short)(u & 0xffffu);
            s_hl[row * PAD + col] = (unsigned short)(u >> 16);
        }
        if (tid < 128) {
            int e = tb + tid;
            s_dst[tid] = (e < E) ? __ldg(dst + e) : 0;
        }
        __syncthreads();
        // gate: 2 threads per edge
        {
            int e = tid >> 1, koff = (tid & 1) * 64;
            const unsigned short* hh = s_hh + e * PAD + koff;
            const unsigned short* hl = s_hl + e * PAD + koff;
            float g = 0.f;
            #pragma unroll 16
            for (int k = 0; k < 64; k++)
                g = fmaf(bfu(hh[k]) + bfu(hl[k]), s_wg[koff + k], g);
            g += __shfl_xor_sync(0xffffffffu, g, 1);
            if ((tid & 1) == 0) s_gate[e] = 1.f / (1.f + __expf(-(g + s_bg[0])));
        }
        __syncthreads();

        #pragma unroll 1
        for (int mt = 0; mt < 8; mt++) {
            float c[4][4] = {};
            #pragma unroll
            for (int kf = 0; kf < 8; kf++) {
                uint32_t Ah[4], Al[4];
                uint32_t aoff = (uint32_t)((mt * 16 + (lane & 15)) * PAD
                                 + kf * 16 + ((lane >> 4) << 3)) * 2;
                ldsm_x4(Ah, smb + E2_HH + aoff);
                ldsm_x4(Al, smb + E2_HL + aoff);
                #pragma unroll
                for (int nf = 0; nf < 4; nf++) {
                    uint32_t Blo[2];
                    uint32_t boff = (uint32_t)((wid * 32 + nf * 8 + (lane & 7)) * PAD
                                     + kf * 16 + (((lane >> 3) & 1) << 3)) * 2;
                    ldsm_x2(Blo, smb + E2_WL + boff);
                    mma_bf16(c[nf], Ah, Bh[nf][kf]);
                    mma_bf16(c[nf], Ah, Blo);
                    mma_bf16(c[nf], Al, Bh[nf][kf]);
                }
            }
            int r0 = mt * 16 + (lane >> 2), r1 = r0 + 8;
            bool k0 = tb + r0 < E, k1 = tb + r1 < E;
            float g0 = s_gate[r0], g1 = s_gate[r1];
            unsigned* p0 = agg + (size_t)s_dst[r0] * 256;
            unsigned* p1 = agg + (size_t)s_dst[r1] * 256;
            #pragma unroll
            for (int nf = 0; nf < 4; nf++) {
                int col0 = wid * 32 + nf * 8 + (lane & 3) * 2;
                float b0v = s_b2f[col0], b1v = s_b2f[col0 + 1];
                float v00 = (c[nf][0] + b0v) * g0, v01 = (c[nf][1] + b1v) * g0;
                float v10 = (c[nf][2] + b0v) * g1, v11 = (c[nf][3] + b1v) * g1;
                if (cat == 0 || cat == 3) {
                    if (k0) atomicAdd((float2*)(p0 + col0), make_float2(v00, v01));
                    if (k1) atomicAdd((float2*)(p1 + col0), make_float2(v10, v11));
                } else if (cat == 1) {
                    if (k0) { atomicMax(p0 + col0, fkey(v00)); atomicMax(p0 + col0 + 1, fkey(v01)); }
                    if (k1) { atomicMax(p1 + col0, fkey(v10)); atomicMax(p1 + col0 + 1, fkey(v11)); }
                } else {
                    if (k0) { atomicMin(p0 + col0, fkey(v00)); atomicMin(p0 + col0 + 1, fkey(v01)); }
                    if (k1) { atomicMin(p1 + col0, fkey(v10)); atomicMin(p1 + col0 + 1, fkey(v11)); }
                }
            }
        }
    }
}

// ---------------- node kernel (fp32, unchanged) ----------------
#define NODE_SMEM_FLOATS (20480 + 8192 + 4096 + 64 + 64 + 64 + 32*321 + 32*68 + 32*132)
__global__ void __launch_bounds__(256, 1) node_kernel(
    const float* __restrict__ x, const unsigned* __restrict__ agg,
    const float* __restrict__ rw, const float* __restrict__ rb,
    const float* __restrict__ w1, const float* __restrict__ b1,
    const float* __restrict__ w2, const float* __restrict__ b2,
    float* __restrict__ out, int N) {
    extern __shared__ float smf[];
    float* s_rw = smf;
    float* s_w1 = smf + 20480;
    float* s_w2 = smf + 28672;
    float* s_rb = smf + 32768;
    float* s_b1 = smf + 32832;
    float* s_b2 = smf + 32896;
    float* s_z  = smf + 32960;
    float* s_nx = smf + 43232;
    float* s_h  = smf + 45408;

    const int tid = threadIdx.x;
    for (int i = tid; i < 5120; i += 256) ((float4*)s_rw)[i] = ((const float4*)rw)[i];
    for (int i = tid; i < 2048; i += 256) ((float4*)s_w1)[i] = ((const float4*)w1)[i];
    for (int i = tid; i < 1024; i += 256) ((float4*)s_w2)[i] = ((const float4*)w2)[i];
    if (tid < 64) { s_rb[tid] = rb[tid]; s_b1[tid] = b1[tid]; s_b2[tid] = b2[tid]; }
    __syncthreads();

    const int n = tid >> 3, jg = tid & 7;
    const int ntiles = (N + 31) >> 5;
    for (int tile = blockIdx.x; tile < ntiles; tile += gridDim.x) {
        const int n0 = tile * 32;
        for (int idx = tid; idx < 32 * 320; idx += 256) {
            int nn = idx / 320, i = idx - nn * 320;
            int gn = n0 + nn;
            float v = 0.f;
            if (gn < N) {
                if (i < 64) v = __ldg(x + (size_t)gn * 64 + i);
                else {
                    int col = i - 64;
                    unsigned raw = __ldg(agg + (size_t)gn * 256 + col);
                    if (col < 64 || col >= 192) v = __uint_as_float(raw);
                    else if (col < 128) v = (raw == 0u) ? 0.f : fdec(raw);
                    else                v = (raw == 0xFFFFFFFFu) ? 0.f : fdec(raw);
                }
            }
            s_z[nn * 321 + i] = v;
        }
        __syncthreads();

        const float* zrow = s_z + n * 321;
        float4 A = ((float4*)s_rb)[jg * 2], B = ((float4*)s_rb)[jg * 2 + 1];
        #pragma unroll 4
        for (int i = 0; i < 320; i++) {
            float zz = zrow[i];
            float4 wA = ((float4*)s_rw)[i * 16 + jg * 2];
            float4 wB = ((float4*)s_rw)[i * 16 + jg * 2 + 1];
            A.x = fmaf(zz, wA.x, A.x); A.y = fmaf(zz, wA.y, A.y);
            A.z = fmaf(zz, wA.z, A.z); A.w = fmaf(zz, wA.w, A.w);
            B.x = fmaf(zz, wB.x, B.x); B.y = fmaf(zz, wB.y, B.y);
            B.z = fmaf(zz, wB.z, B.z); B.w = fmaf(zz, wB.w, B.w);
        }
        ((float4*)(s_nx + n * 68))[jg * 2] = A;
        ((float4*)(s_nx + n * 68))[jg * 2 + 1] = B;
        __syncwarp();

        float hacc[16];
        #pragma unroll
        for (int tt = 0; tt < 16; tt++) hacc[tt] = s_b1[jg * 16 + tt];
        #pragma unroll 2
        for (int i = 0; i < 64; i++) {
            float in = zrow[i];
            const float* wr = s_w1 + i * 64 + jg * 16;
            #pragma unroll
            for (int tt = 0; tt < 16; tt++) hacc[tt] = fmaf(in, wr[tt], hacc[tt]);
        }
        const float* nxrow = s_nx + n * 68;
        #pragma unroll 2
        for (int i = 0; i < 64; i++) {
            float in = nxrow[i];
            const float* wr = s_w1 + (64 + i) * 64 + jg * 16;
            #pragma unroll
            for (int tt = 0; tt < 16; tt++) hacc[tt] = fmaf(in, wr[tt], hacc[tt]);
        }
        #pragma unroll
        for (int tt = 0; tt < 16; tt++) s_h[n * 132 + jg * 16 + tt] = fmaxf(hacc[tt], 0.f);
        __syncwarp();

        float4 O0 = ((float4*)s_b2)[jg * 2], O1 = ((float4*)s_b2)[jg * 2 + 1];
        const float* hrow = s_h + n * 132;
        #pragma unroll 4
        for (int i = 0; i < 64; i++) {
            float hv = hrow[i];
            float4 wA = ((float4*)s_w2)[i * 16 + jg * 2];
            float4 wB = ((float4*)s_w2)[i * 16 + jg * 2 + 1];
            O0.x = fmaf(hv, wA.x, O0.x); O0.y = fmaf(hv, wA.y, O0.y);
            O0.z = fmaf(hv, wA.z, O0.z); O0.w = fmaf(hv, wA.w, O0.w);
            O1.x = fmaf(hv, wB.x, O1.x); O1.y = fmaf(hv, wB.y, O1.y);
            O1.z = fmaf(hv, wB.z, O1.z); O1.w = fmaf(hv, wB.w, O1.w);
        }
        int gn = n0 + n;
        if (gn < N) {
            ((float4*)(out + (size_t)gn * 64 + jg * 8))[0] = O0;
            ((float4*)(out + (size_t)gn * 64 + jg * 8))[1] = O1;
        }
        __syncthreads();
    }
}

// ---------------------------------------------------------------------------
extern "C" void kernel_launch(void* const* d_in, const int* in_sizes, int n_in,
                              void* d_out, int out_size) {
    const float* nf_gc  = (const float*)d_in[0];
    const float* nf_gs  = (const float*)d_in[1];
    const float* w_gc   = (const float*)d_in[2];
    const float* b_gc   = (const float*)d_in[3];
    const float* w_gs   = (const float*)d_in[4];
    const float* b_gs   = (const float*)d_in[5];
    const float* s2c_w1 = (const float*)d_in[6];
    const float* s2c_b1 = (const float*)d_in[7];
    const float* s2c_w2 = (const float*)d_in[8];
    const float* s2c_b2 = (const float*)d_in[9];
    const float* s2c_rw = (const float*)d_in[10];
    const float* s2c_rb = (const float*)d_in[11];
    const float* c2s_w1 = (const float*)d_in[12];
    const float* c2s_b1 = (const float*)d_in[13];
    const float* c2s_w2 = (const float*)d_in[14];
    const float* c2s_b2 = (const float*)d_in[15];
    const float* c2s_rw = (const float*)d_in[16];
    const float* c2s_rb = (const float*)d_in[17];
    const float* gc_w1  = (const float*)d_in[18];
    const float* gc_b1  = (const float*)d_in[19];
    const float* gc_w2  = (const float*)d_in[20];
    const float* gc_b2  = (const float*)d_in[21];
    const float* gs_w1  = (const float*)d_in[22];
    const float* gs_b1  = (const float*)d_in[23];
    const float* gs_w2  = (const float*)d_in[24];
    const float* gs_b2  = (const float*)d_in[25];
    const int* s2c_src  = (const int*)d_in[26];
    const int* s2c_dst  = (const int*)d_in[27];
    const int* c2s_src  = (const int*)d_in[28];
    const int* c2s_dst  = (const int*)d_in[29];

    const int FGC = in_sizes[2] / 64;
    const int FGS = in_sizes[4] / 64;
    const int NGC = in_sizes[0] / FGC;
    const int NGS = in_sizes[1] / FGS;
    const int E1 = in_sizes[26];
    const int E2 = in_sizes[28];

    float *gcx, *gsx;
    unsigned *aggc, *aggs, *hbuf;
    cudaGetSymbolAddress((void**)&gcx, g_gcx);
    cudaGetSymbolAddress((void**)&gsx, g_gsx);
    cudaGetSymbolAddress((void**)&aggc, g_aggc);
    cudaGetSymbolAddress((void**)&aggs, g_aggs);
    cudaGetSymbolAddress((void**)&hbuf, g_hbuf);

    const int NODE_SMEM = NODE_SMEM_FLOATS * 4;
    cudaFuncSetAttribute(edge_l1_kernel, cudaFuncAttributeMaxDynamicSharedMemorySize, E1_SMEM);
    cudaFuncSetAttribute(edge_l2_kernel, cudaFuncAttributeMaxDynamicSharedMemorySize, E2_SMEM);
    cudaFuncSetAttribute(node_kernel, cudaFuncAttributeMaxDynamicSharedMemorySize, NODE_SMEM);

    embed_kernel<<<(NGC * 64 + 255) / 256, 256>>>(nf_gc, w_gc, b_gc, gcx, NGC, FGC);
    embed_kernel<<<(NGS * 64 + 255) / 256, 256>>>(nf_gs, w_gs, b_gs, gsx, NGS, FGS);
    init_agg_kernel<<<(NGC * 256 + 255) / 256, 256>>>(aggc, NGC * 256);
    init_agg_kernel<<<(NGS * 256 + 255) / 256, 256>>>(aggs, NGS * 256);

    // gs -> gc
    edge_l1_kernel<<<152, 256, E1_SMEM>>>(gsx, gcx, s2c_src, s2c_dst,
                                          s2c_w1, s2c_b1, hbuf, E1);
    edge_l2_kernel<<<152, 256, E2_SMEM>>>(s2c_dst, s2c_w2, s2c_b2, hbuf, aggc, E1);
    // gc -> gs
    edge_l1_kernel<<<152, 256, E1_SMEM>>>(gcx, gsx, c2s_src, c2s_dst,
                                          c2s_w1, c2s_b1, hbuf, E2);
    edge_l2_kernel<<<152, 256, E2_SMEM>>>(c2s_dst, c2s_w2, c2s_b2, hbuf, aggs, E2);

    float* out = (float*)d_out;
    node_kernel<<<152, 256, NODE_SMEM>>>(gcx, aggc, s2c_rw, s2c_rb,
                                         gc_w1, gc_b1, gc_w2, gc_b2, out, NGC);
    node_kernel<<<152, 256, NODE_SMEM>>>(gsx, aggs, c2s_rw, c2s_rb,
                                         gs_w1, gs_b1, gs_w2, gs_b2, out + (size_t)NGC * 64, NGS);
}